// round 11
// baseline (speedup 1.0000x reference)
#include <cuda_runtime.h>

// CostVolume: left,right [B,C,H,W] f32 -> out [B,2C,D,H,W] f32
//   out[b, c,      d, h, w] = (w+d < W) ? left [b,c,h,w+d] : 0
//   out[b, C + c,  d, h, w] = (w-d >= 0)? right[b,c,h,w-d] : 0
//
// Fixed shapes: B=2, C=32, H=128, W=256, D=32.
//
// FINAL (measured best 76.3us = ~7.25 TB/s effective, ~90% of HBM3e spec).
// Converged design, validated over 10 rounds of ncu evidence:
//   - One 512-thread CTA per pair of adjacent h rows (grid 4096).
//   - Rows staged once in zero-padded smem (pads encode boundary zeros, so
//     the store path has no conditionals).
//   - Each thread: 20-float register window (5 x LDS.128) covering its
//     4-float output column across its 16 disparities, then ONE
//     uninterrupted burst of 16 x STG.128 with st.global.cs (evict-first:
//     keeps L2 write aggregation, avoids dirty-line retention of the
//     536 MB write-once stream).
//   - Measured dead ends: .wt (+8us, loses L2 write combining), STG.256
//     (+8us, sliding window forces per-store octet rebuilds, regs 38->54),
//     4-row fusion w/ interleaved reloads (+6us, breaks store burst),
//     syncless direct-LDG windows (neutral), occupancy 41%->69% (BW flat
//     at every point => HBM write path is the binding ceiling).

namespace {
constexpr int B = 2;
constexpr int C = 32;
constexpr int H = 128;
constexpr int W = 256;
constexpr int D = 32;
constexpr int PADQ = 72;   // float4s per padded row buffer
}

__device__ __forceinline__ void stcs128(float* p, float4 v) {
    __stcs(reinterpret_cast<float4*>(p), v);
}

__global__ __launch_bounds__(512)
void cost_volume_kernel(const float* __restrict__ left,
                        const float* __restrict__ right,
                        float* __restrict__ out) {
    // Per row r (0..1):
    //   slbuf[r] floats: [0..255] = left row, [256..287] = zero tail.
    //   srbuf[r] floats: [0..31] = zero head, [32..287] = right row
    //                    (srbuf float j holds right_row[j-32]).
    __shared__ float4 slbuf[2][PADQ];
    __shared__ float4 srbuf[2][PADQ];

    const int blk = blockIdx.x;            // b*C*(H/2) + c*(H/2) + hp
    const int hp = blk & (H / 2 - 1);      // 64 row pairs per (b,c)
    const int c  = (blk >> 6) & (C - 1);
    const int b  = blk >> 11;

    const int tid   = threadIdx.x;         // 0..511
    const int rsub  = tid >> 8;            // row within pair
    const int t256  = tid & 255;
    const int half  = t256 >> 7;           // 0 = left, 1 = right
    const int dhalf = (t256 >> 6) & 1;     // d block
    const int l64   = t256 & 63;           // float4 column
    const int w4    = l64 << 2;
    const int d0    = dhalf << 4;          // 0 or 16
    const int h     = hp * 2 + rsub;

    const size_t in_off = ((((size_t)b * C + c) * H) + h) * W;

    // ---- stage row pair + zero pads (per 256-thread group) ----
    if (t256 < 64) {
        slbuf[rsub][t256] = reinterpret_cast<const float4*>(left + in_off)[t256];
    } else if (t256 < 128) {
        srbuf[rsub][8 + (t256 - 64)] =
            reinterpret_cast<const float4*>(right + in_off)[t256 - 64];
    } else if (t256 < 136) {
        slbuf[rsub][64 + (t256 - 128)] = make_float4(0.f, 0.f, 0.f, 0.f);
    } else if (t256 < 144) {
        srbuf[rsub][t256 - 136] = make_float4(0.f, 0.f, 0.f, 0.f);
    }
    __syncthreads();

    // ---- 20-float register window (5 x LDS.128) ----
    // Left  thread: f[k] = left_row [w4 + d0 + k],      k = 0..19
    // Right thread: f[k] = right_row[w4 - d0 - 16 + k], k = 0..19
    float f[20];
    {
        const float4* buf  = half ? srbuf[rsub] : slbuf[rsub];
        const int     base = half ? (l64 + 4 - 4 * dhalf) : (l64 + 4 * dhalf);
        #pragma unroll
        for (int i = 0; i < 5; i++) {
            float4 q = buf[base + i];
            f[4 * i + 0] = q.x;
            f[4 * i + 1] = q.y;
            f[4 * i + 2] = q.z;
            f[4 * i + 3] = q.w;
        }
    }

    // ---- emit 16 disparity planes (one uninterrupted streaming burst) ----
    const size_t dstride = (size_t)H * W;  // 32768 floats per d-plane
    float* dst = out
        + ((size_t)(b * 2 * C + half * C + c) * D + d0) * dstride
        + (size_t)h * W + w4;

    if (half == 0) {
        // d = d0 + dd: out = left_row[w4+d .. w4+d+3] = f[dd .. dd+3]
        #pragma unroll
        for (int dd = 0; dd < 16; dd++) {
            float4 v = make_float4(f[dd], f[dd + 1], f[dd + 2], f[dd + 3]);
            stcs128(dst + (size_t)dd * dstride, v);
        }
    } else {
        // d = d0 + dd: out = right_row[w4-d .. w4-d+3] = f[16-dd .. 19-dd]
        #pragma unroll
        for (int dd = 0; dd < 16; dd++) {
            float4 v = make_float4(f[16 - dd], f[17 - dd], f[18 - dd], f[19 - dd]);
            stcs128(dst + (size_t)dd * dstride, v);
        }
    }
}

extern "C" void kernel_launch(void* const* d_in, const int* in_sizes, int n_in,
                              void* d_out, int out_size) {
    const float* left  = (const float*)d_in[0];
    const float* right = (const float*)d_in[1];
    float* out = (float*)d_out;

    (void)in_sizes; (void)n_in; (void)out_size;

    const int grid = B * C * (H / 2);  // 4096 CTAs
    cost_volume_kernel<<<grid, 512>>>(left, right, out);
}

// round 13
// speedup vs baseline: 1.0058x; 1.0058x over previous
#include <cuda_runtime.h>

// CostVolume: left,right [B,C,H,W] f32 -> out [B,2C,D,H,W] f32
//   out[b, c,      d, h, w] = (w+d < W) ? left [b,c,h,w+d] : 0
//   out[b, C + c,  d, h, w] = (w-d >= 0)? right[b,c,h,w-d] : 0
//
// Fixed shapes: B=2, C=32, H=128, W=256, D=32.
//
// FINAL CONVERGED KERNEL (76.3-77.9us band, ~7.1 TB/s effective = ~89% of
// HBM3e spec on a 537 MB write-once stream). 11 rounds of ncu evidence:
//   - One 512-thread CTA per pair of adjacent h rows (grid 4096).
//   - Rows staged once in zero-padded smem (pads encode boundary zeros:
//     the store path has zero conditionals).
//   - Each thread: 20-float register window (5 x LDS.128) covering its
//     4-float output column across its 16 disparities, then ONE
//     uninterrupted burst of 16 x STG.128 via st.global.cs (evict-first:
//     keeps L2 write aggregation, avoids dirty-line retention).
//   - Proven dead ends: .wt (+8us), STG.256 (+8us, octet rebuilds),
//     4-row interleaved fusion (+6us), syncless LDG windows (neutral),
//     occupancy 41-69% sweep (DRAM% flat => external write-path ceiling),
//     zero-wedge skipping (impossible: harness poisons d_out per run).

namespace {
constexpr int B = 2;
constexpr int C = 32;
constexpr int H = 128;
constexpr int W = 256;
constexpr int D = 32;
constexpr int PADQ = 72;   // float4s per padded row buffer
}

__device__ __forceinline__ void stcs128(float* p, float4 v) {
    __stcs(reinterpret_cast<float4*>(p), v);
}

__global__ __launch_bounds__(512)
void cost_volume_kernel(const float* __restrict__ left,
                        const float* __restrict__ right,
                        float* __restrict__ out) {
    // Per row r (0..1):
    //   slbuf[r] floats: [0..255] = left row, [256..287] = zero tail.
    //   srbuf[r] floats: [0..31] = zero head, [32..287] = right row
    //                    (srbuf float j holds right_row[j-32]).
    __shared__ float4 slbuf[2][PADQ];
    __shared__ float4 srbuf[2][PADQ];

    const int blk = blockIdx.x;            // b*C*(H/2) + c*(H/2) + hp
    const int hp = blk & (H / 2 - 1);      // 64 row pairs per (b,c)
    const int c  = (blk >> 6) & (C - 1);
    const int b  = blk >> 11;

    const int tid   = threadIdx.x;         // 0..511
    const int rsub  = tid >> 8;            // row within pair
    const int t256  = tid & 255;
    const int half  = t256 >> 7;           // 0 = left, 1 = right
    const int dhalf = (t256 >> 6) & 1;     // d block
    const int l64   = t256 & 63;           // float4 column
    const int w4    = l64 << 2;
    const int d0    = dhalf << 4;          // 0 or 16
    const int h     = hp * 2 + rsub;

    const size_t in_off = ((((size_t)b * C + c) * H) + h) * W;

    // ---- stage row pair + zero pads (per 256-thread group) ----
    if (t256 < 64) {
        slbuf[rsub][t256] = reinterpret_cast<const float4*>(left + in_off)[t256];
    } else if (t256 < 128) {
        srbuf[rsub][8 + (t256 - 64)] =
            reinterpret_cast<const float4*>(right + in_off)[t256 - 64];
    } else if (t256 < 136) {
        slbuf[rsub][64 + (t256 - 128)] = make_float4(0.f, 0.f, 0.f, 0.f);
    } else if (t256 < 144) {
        srbuf[rsub][t256 - 136] = make_float4(0.f, 0.f, 0.f, 0.f);
    }
    __syncthreads();

    // ---- 20-float register window (5 x LDS.128) ----
    // Left  thread: f[k] = left_row [w4 + d0 + k],      k = 0..19
    // Right thread: f[k] = right_row[w4 - d0 - 16 + k], k = 0..19
    float f[20];
    {
        const float4* buf  = half ? srbuf[rsub] : slbuf[rsub];
        const int     base = half ? (l64 + 4 - 4 * dhalf) : (l64 + 4 * dhalf);
        #pragma unroll
        for (int i = 0; i < 5; i++) {
            float4 q = buf[base + i];
            f[4 * i + 0] = q.x;
            f[4 * i + 1] = q.y;
            f[4 * i + 2] = q.z;
            f[4 * i + 3] = q.w;
        }
    }

    // ---- emit 16 disparity planes (one uninterrupted streaming burst) ----
    const size_t dstride = (size_t)H * W;  // 32768 floats per d-plane
    float* dst = out
        + ((size_t)(b * 2 * C + half * C + c) * D + d0) * dstride
        + (size_t)h * W + w4;

    if (half == 0) {
        // d = d0 + dd: out = left_row[w4+d .. w4+d+3] = f[dd .. dd+3]
        #pragma unroll
        for (int dd = 0; dd < 16; dd++) {
            float4 v = make_float4(f[dd], f[dd + 1], f[dd + 2], f[dd + 3]);
            stcs128(dst + (size_t)dd * dstride, v);
        }
    } else {
        // d = d0 + dd: out = right_row[w4-d .. w4-d+3] = f[16-dd .. 19-dd]
        #pragma unroll
        for (int dd = 0; dd < 16; dd++) {
            float4 v = make_float4(f[16 - dd], f[17 - dd], f[18 - dd], f[19 - dd]);
            stcs128(dst + (size_t)dd * dstride, v);
        }
    }
}

extern "C" void kernel_launch(void* const* d_in, const int* in_sizes, int n_in,
                              void* d_out, int out_size) {
    const float* left  = (const float*)d_in[0];
    const float* right = (const float*)d_in[1];
    float* out = (float*)d_out;

    (void)in_sizes; (void)n_in; (void)out_size;

    const int grid = B * C * (H / 2);  // 4096 CTAs
    cost_volume_kernel<<<grid, 512>>>(left, right, out);
}